// round 16
// baseline (speedup 1.0000x reference)
#include <cuda_runtime.h>
#include <cuda_bf16.h>
#include <cstdint>

// Problem shape (fixed by the dataset): N=100000 nodes, 256 in-feats, 64 out-feats, E=3.2M edges.
#define NMAX   100000
#define EMAX   3200000
#define KIN    256
#define COUT   64
#define NBLK   ((NMAX + 255) / 256)   // 391
#define TM     128
#define TKC    16
#define GEMM_BLOCKS ((NMAX + TM - 1) / TM)   // 782

// Scratch (no cudaMalloc allowed).
__device__ float g_h[(size_t)NMAX * COUT];   // h = x@W, normalized in-place to h' by norm kernel
__device__ float g_dinv[NMAX];               // rsqrt(deg+1)
__device__ int   g_degi[NMAX];               // incoming-edge count (excl. self-loop)
__device__ int   g_off[NMAX];                // CSR offsets (exclusive scan of degi)
__device__ int   g_cur[NMAX];                // fill cursors
__device__ int   g_srcl[EMAX];               // CSR: source node per incoming edge
__device__ unsigned long long g_state[NBLK]; // lookback: (flag<<32)|sum; 1=aggregate,2=prefix
__device__ int   g_tkt;                      // scan ticket
__device__ int   g_idx64;                    // 1 if edge_index is int64, 0 if int32

// ---------------------------------------------------------------------------
// helpers
// ---------------------------------------------------------------------------
__device__ __forceinline__ int load_col(const void* ei, int E, int e) {
    if (g_idx64) return (int)__ldg(&((const long long*)ei)[(size_t)E + e]);
    return __ldg(&((const int*)ei)[(size_t)E + e]);
}
__device__ __forceinline__ int load_row(const void* ei, int e) {
    if (g_idx64) return (int)__ldg(&((const long long*)ei)[e]);
    return __ldg(&((const int*)ei)[e]);
}

__device__ __forceinline__ void split_tf32(float v, float& hi, float& lo) {
    uint32_t u;
    asm("cvt.rna.tf32.f32 %0, %1;" : "=r"(u) : "f"(v));
    hi = __uint_as_float(u);
    float l = v - hi;
    asm("cvt.rna.tf32.f32 %0, %1;" : "=r"(u) : "f"(l));
    lo = __uint_as_float(u);
}

__device__ __forceinline__ void mma_tf32(float* c, const uint32_t* a,
                                         uint32_t b0, uint32_t b1) {
    asm volatile("mma.sync.aligned.m16n8k8.row.col.f32.tf32.tf32.f32 "
                 "{%0,%1,%2,%3}, {%4,%5,%6,%7}, {%8,%9}, {%0,%1,%2,%3};"
                 : "+f"(c[0]), "+f"(c[1]), "+f"(c[2]), "+f"(c[3])
                 : "r"(a[0]), "r"(a[1]), "r"(a[2]), "r"(a[3]),
                   "r"(b0), "r"(b1));
}

// ---------------------------------------------------------------------------
// 1) detect dtype (block 0) + zero degi / scan state (blocks 1..)
// ---------------------------------------------------------------------------
__global__ void detect_zero_kernel(const long long* __restrict__ e64, int n, int nblk) {
    if (blockIdx.x == 0) {
        __shared__ int bad;
        if (threadIdx.x == 0) bad = 0;
        __syncthreads();
        for (int i = threadIdx.x; i < 4096; i += blockDim.x) {
            long long v = e64[i];
            if (v < 0 || v >= (long long)n) atomicOr(&bad, 1);
        }
        __syncthreads();
        if (threadIdx.x == 0) g_idx64 = bad ? 0 : 1;
    } else {
        int i = (blockIdx.x - 1) * 256 + threadIdx.x;
        if (i < n) g_degi[i] = 0;
        if (i < nblk) g_state[i] = 0ULL;
        if (i == 0) g_tkt = 0;
    }
}

// ---------------------------------------------------------------------------
// 2) degi[col[e]] += 1, 4 edges/thread  (fire-and-forget -> REDG)
// ---------------------------------------------------------------------------
__global__ void count_kernel(const void* __restrict__ ei, int E) {
    int e0 = (blockIdx.x * 256 + threadIdx.x) * 4;
#pragma unroll
    for (int k = 0; k < 4; k++) {
        int e = e0 + k;
        if (e < E) atomicAdd(&g_degi[load_col(ei, E, e)], 1);
    }
}

// ---------------------------------------------------------------------------
// 3) gemm: h = x @ W (RAW) via 3xTF32 MMA, 128x64 tile, 8 warps. (pure R8 form)
// ---------------------------------------------------------------------------
__global__ __launch_bounds__(256) void gemm_kernel(const float* __restrict__ x,
                                                   const float* __restrict__ W,
                                                   int n) {
    __shared__ float xs_h[TM][20];    // stride 20: frag reads conflict-free
    __shared__ float xs_l[TM][20];
    __shared__ float ws_h[TKC][72];   // stride 72 (== 8 mod 32): conflict-free
    __shared__ float ws_l[TKC][72];

    const int t    = threadIdx.x;
    const int warp = t >> 5;
    const int lane = t & 31;
    const int lq   = lane >> 2;   // groupID 0..7
    const int kc   = lane & 3;    // threadID_in_group 0..3
    const int wrow = warp * 16;
    const int row0 = blockIdx.x * TM;

    float acc[8][4];
#pragma unroll
    for (int i = 0; i < 8; i++)
#pragma unroll
        for (int j = 0; j < 4; j++) acc[i][j] = 0.0f;

#pragma unroll
    for (int k0 = 0; k0 < KIN; k0 += TKC) {
#pragma unroll
        for (int j = 0; j < 2; j++) {
            int i  = t + j * 256;        // 0..511
            int r  = i >> 2;             // 0..127
            int kq = (i & 3) << 2;       // 0,4,8,12
            int gr = row0 + r;
            float4 v = make_float4(0.f, 0.f, 0.f, 0.f);
            if (gr < n) v = *(const float4*)(x + (size_t)gr * KIN + k0 + kq);
            float4 h4, l4;
            split_tf32(v.x, h4.x, l4.x);
            split_tf32(v.y, h4.y, l4.y);
            split_tf32(v.z, h4.z, l4.z);
            split_tf32(v.w, h4.w, l4.w);
            *(float4*)&xs_h[r][kq] = h4;
            *(float4*)&xs_l[r][kq] = l4;
        }
        {
            int kk = t >> 4;             // 0..15
            int c  = (t & 15) << 2;      // 0..60
            float4 v = *(const float4*)(W + (size_t)(k0 + kk) * COUT + c);
            float4 h4, l4;
            split_tf32(v.x, h4.x, l4.x);
            split_tf32(v.y, h4.y, l4.y);
            split_tf32(v.z, h4.z, l4.z);
            split_tf32(v.w, h4.w, l4.w);
            *(float4*)&ws_h[kk][c] = h4;
            *(float4*)&ws_l[kk][c] = l4;
        }
        __syncthreads();

#pragma unroll
        for (int kk = 0; kk < TKC; kk += 8) {
            uint32_t ah[4], al[4];
            const int rA = wrow + lq;
            ah[0] = __float_as_uint(xs_h[rA][kk + kc]);
            ah[1] = __float_as_uint(xs_h[rA + 8][kk + kc]);
            ah[2] = __float_as_uint(xs_h[rA][kk + kc + 4]);
            ah[3] = __float_as_uint(xs_h[rA + 8][kk + kc + 4]);
            al[0] = __float_as_uint(xs_l[rA][kk + kc]);
            al[1] = __float_as_uint(xs_l[rA + 8][kk + kc]);
            al[2] = __float_as_uint(xs_l[rA][kk + kc + 4]);
            al[3] = __float_as_uint(xs_l[rA + 8][kk + kc + 4]);
#pragma unroll
            for (int nt = 0; nt < 8; nt++) {
                int col = nt * 8 + lq;
                uint32_t bh0 = __float_as_uint(ws_h[kk + kc][col]);
                uint32_t bh1 = __float_as_uint(ws_h[kk + kc + 4][col]);
                uint32_t bl0 = __float_as_uint(ws_l[kk + kc][col]);
                uint32_t bl1 = __float_as_uint(ws_l[kk + kc + 4][col]);
                mma_tf32(acc[nt], ah, bh0, bh1);   // hi*hi
                mma_tf32(acc[nt], al, bh0, bh1);   // lo*hi
                mma_tf32(acc[nt], ah, bl0, bl1);   // hi*lo
            }
        }
        __syncthreads();
    }

    // epilogue: store RAW h (normalized later)
    const int gr0 = row0 + wrow + lq;
    const int gr1 = gr0 + 8;
#pragma unroll
    for (int nt = 0; nt < 8; nt++) {
        int col = nt * 8 + kc * 2;
        if (gr0 < n) *(float2*)(g_h + (size_t)gr0 * COUT + col) = make_float2(acc[nt][0], acc[nt][1]);
        if (gr1 < n) *(float2*)(g_h + (size_t)gr1 * COUT + col) = make_float2(acc[nt][2], acc[nt][3]);
    }
}

// ---------------------------------------------------------------------------
// 4) single-pass exclusive scan (decoupled lookback, ticket-ordered blocks)
//    emits g_off, g_cur, g_dinv.
// ---------------------------------------------------------------------------
__global__ __launch_bounds__(256) void scan_kernel(int n) {
    __shared__ int sbid;
    __shared__ int wsum[8];
    __shared__ int sbase;
    if (threadIdx.x == 0) sbid = atomicAdd(&g_tkt, 1);
    __syncthreads();
    const int bid = sbid;
    const int i = bid * 256 + threadIdx.x;
    const int lane = threadIdx.x & 31, wid = threadIdx.x >> 5;

    int v = (i < n) ? g_degi[i] : 0;
    int p = v;
#pragma unroll
    for (int o = 1; o < 32; o <<= 1) {
        int t = __shfl_up_sync(0xffffffffu, p, o);
        if (lane >= o) p += t;
    }
    if (lane == 31) wsum[wid] = p;
    __syncthreads();
    if (wid == 0) {
        int s = (lane < 8) ? wsum[lane] : 0;
#pragma unroll
        for (int o = 1; o < 8; o <<= 1) {
            int t = __shfl_up_sync(0xffffffffu, s, o);
            if (lane >= o) s += t;
        }
        if (lane < 8) wsum[lane] = s;   // inclusive warp sums
    }
    __syncthreads();
    const int base  = wid ? wsum[wid - 1] : 0;
    const int total = wsum[7];          // block sum

    if (threadIdx.x == 0) {
        if (bid == 0) {
            atomicExch(&g_state[0], (2ULL << 32) | (unsigned)total);
            sbase = 0;
        } else {
            atomicExch(&g_state[bid], (1ULL << 32) | (unsigned)total);
            int run = 0;
            for (int j = bid - 1;; j--) {
                unsigned long long s;
                do { s = *(volatile unsigned long long*)&g_state[j]; } while ((s >> 32) == 0);
                run += (int)(unsigned)s;
                if ((s >> 32) == 2ULL) break;
            }
            atomicExch(&g_state[bid], (2ULL << 32) | (unsigned)(run + total));
            sbase = run;
        }
    }
    __syncthreads();
    if (i < n) {
        int o = sbase + base + p - v;   // exclusive prefix
        g_off[i]  = o;
        g_cur[i]  = o;
        g_dinv[i] = rsqrtf((float)v + 1.0f);
    }
}

// ---------------------------------------------------------------------------
// 5) norm: g_h *= dinv[node]  (h -> h'), float4 per thread
// ---------------------------------------------------------------------------
__global__ void norm_kernel(int n) {
    int idx = blockIdx.x * 256 + threadIdx.x;        // over N*16 float4s
    if (idx < n * (COUT / 4)) {
        int node = idx >> 4;
        float d = g_dinv[node];
        float4 v = *(float4*)(g_h + (size_t)idx * 4);
        v.x *= d; v.y *= d; v.z *= d; v.w *= d;
        *(float4*)(g_h + (size_t)idx * 4) = v;
    }
}

// ---------------------------------------------------------------------------
// 6) fill CSR: g_srcl[cur[col]++] = row.  8 edges/thread, loads BATCHED first
//    (MLP=8 on the coalesced index loads), then independent atomics+stores.
// ---------------------------------------------------------------------------
__global__ void fill_kernel(const void* __restrict__ ei, int E) {
    int base = (blockIdx.x * 256 + threadIdx.x) * 8;
    if (base >= E) return;
    int r[8], c[8];
    const int cnt = min(8, E - base);
#pragma unroll
    for (int k = 0; k < 8; k++) {
        if (k < cnt) {
            r[k] = load_row(ei, base + k);
            c[k] = load_col(ei, E, base + k);
        }
    }
#pragma unroll
    for (int k = 0; k < 8; k++) {
        if (k < cnt) {
            int pos = atomicAdd(&g_cur[c[k]], 1);
            g_srcl[pos] = r[k];
        }
    }
}

// ---------------------------------------------------------------------------
// 7) gather + finalize: one warp per node, float2 lanes, 8-way unroll of the
//    R8-proven load pattern (same shape, deeper MLP).  Typical degree 32 =
//    exactly 4 iterations of 8.
//    out[i] = (sum_s h'[s] + h'[i]) * dinv[i] + b
// ---------------------------------------------------------------------------
__global__ __launch_bounds__(256) void gather_kernel(const float* __restrict__ b,
                                                     float* __restrict__ out, int n) {
    int warp = (blockIdx.x * 256 + threadIdx.x) >> 5;
    int lane = threadIdx.x & 31;
    if (warp >= n) return;

    const int beg = g_off[warp];
    const int d   = g_degi[warp];

    float2 a0 = make_float2(0.f, 0.f);
    float2 a1 = make_float2(0.f, 0.f);
    float2 a2 = make_float2(0.f, 0.f);
    float2 a3 = make_float2(0.f, 0.f);
    float2 a4 = make_float2(0.f, 0.f);
    float2 a5 = make_float2(0.f, 0.f);
    float2 a6 = make_float2(0.f, 0.f);
    float2 a7 = make_float2(0.f, 0.f);

    for (int j0 = 0; j0 < d; j0 += 32) {
        int m  = min(32, d - j0);
        int sl = (lane < m) ? g_srcl[beg + j0 + lane] : 0;
        int j  = 0;
        for (; j + 7 < m; j += 8) {
            int s0 = __shfl_sync(0xffffffffu, sl, j);
            int s1 = __shfl_sync(0xffffffffu, sl, j + 1);
            int s2 = __shfl_sync(0xffffffffu, sl, j + 2);
            int s3 = __shfl_sync(0xffffffffu, sl, j + 3);
            int s4 = __shfl_sync(0xffffffffu, sl, j + 4);
            int s5 = __shfl_sync(0xffffffffu, sl, j + 5);
            int s6 = __shfl_sync(0xffffffffu, sl, j + 6);
            int s7 = __shfl_sync(0xffffffffu, sl, j + 7);
            float2 v0 = *(const float2*)(g_h + (size_t)s0 * COUT + lane * 2);
            float2 v1 = *(const float2*)(g_h + (size_t)s1 * COUT + lane * 2);
            float2 v2 = *(const float2*)(g_h + (size_t)s2 * COUT + lane * 2);
            float2 v3 = *(const float2*)(g_h + (size_t)s3 * COUT + lane * 2);
            float2 v4 = *(const float2*)(g_h + (size_t)s4 * COUT + lane * 2);
            float2 v5 = *(const float2*)(g_h + (size_t)s5 * COUT + lane * 2);
            float2 v6 = *(const float2*)(g_h + (size_t)s6 * COUT + lane * 2);
            float2 v7 = *(const float2*)(g_h + (size_t)s7 * COUT + lane * 2);
            a0.x += v0.x; a0.y += v0.y;
            a1.x += v1.x; a1.y += v1.y;
            a2.x += v2.x; a2.y += v2.y;
            a3.x += v3.x; a3.y += v3.y;
            a4.x += v4.x; a4.y += v4.y;
            a5.x += v5.x; a5.y += v5.y;
            a6.x += v6.x; a6.y += v6.y;
            a7.x += v7.x; a7.y += v7.y;
        }
        for (; j < m; j++) {
            int s0 = __shfl_sync(0xffffffffu, sl, j);
            float2 v0 = *(const float2*)(g_h + (size_t)s0 * COUT + lane * 2);
            a0.x += v0.x; a0.y += v0.y;
        }
    }

    float2 hs = *(const float2*)(g_h + (size_t)warp * COUT + lane * 2);
    float dinv = g_dinv[warp];
    float2 bb = *(const float2*)(b + lane * 2);
    float2 o;
    o.x = (a0.x + a1.x + a2.x + a3.x + a4.x + a5.x + a6.x + a7.x + hs.x) * dinv + bb.x;
    o.y = (a0.y + a1.y + a2.y + a3.y + a4.y + a5.y + a6.y + a7.y + hs.y) * dinv + bb.y;
    *(float2*)(out + (size_t)warp * COUT + lane * 2) = o;
}

// ---------------------------------------------------------------------------
// Launch: fork-join two streams inside graph capture.
//   origin (legacy) stream: gemm ............ wait(scan) norm  wait(fill) gather
//   side stream sB:         detect count scan [ev_scan]  fill  [ev_fill]
// ---------------------------------------------------------------------------
extern "C" void kernel_launch(void* const* d_in, const int* in_sizes, int n_in,
                              void* d_out, int out_size) {
    const float* x  = (const float*)d_in[0];
    const void*  ei = d_in[1];                 // int64 or int32, detected on device
    const float* W  = (const float*)d_in[2];
    const float* b  = (const float*)d_in[3];
    float* out = (float*)d_out;

    const int n = in_sizes[0] / KIN;           // 100000
    const int E = in_sizes[1] / 2;             // 3200000
    const int nblk = (n + 255) / 256;          // 391
    const int cnt_blocks  = (E + 1023) / 1024; // 4 edges/thread
    const int fill_blocks = (E + 2047) / 2048; // 8 edges/thread
    const int norm_blocks = (n * (COUT / 4) + 255) / 256;

    // One-time resource creation (host-side only; no device memory).
    static cudaStream_t sB = nullptr;
    static cudaEvent_t ev_start = nullptr, ev_scan = nullptr, ev_fill = nullptr;
    if (sB == nullptr) {
        cudaStreamCreateWithFlags(&sB, cudaStreamNonBlocking);
        cudaEventCreateWithFlags(&ev_start, cudaEventDisableTiming);
        cudaEventCreateWithFlags(&ev_scan,  cudaEventDisableTiming);
        cudaEventCreateWithFlags(&ev_fill,  cudaEventDisableTiming);
    }

    // Fork side stream from origin.
    cudaEventRecord(ev_start, 0);
    cudaStreamWaitEvent(sB, ev_start, 0);

    // Side chain: detect -> count -> scan -> fill
    detect_zero_kernel<<<nblk + 1, 256, 0, sB>>>((const long long*)ei, n, nblk);
    count_kernel<<<cnt_blocks, 256, 0, sB>>>(ei, E);
    scan_kernel<<<nblk, 256, 0, sB>>>(n);
    cudaEventRecord(ev_scan, sB);
    fill_kernel<<<fill_blocks, 256, 0, sB>>>(ei, E);
    cudaEventRecord(ev_fill, sB);

    // Origin chain: gemm (overlaps side chain) -> norm -> gather
    gemm_kernel<<<GEMM_BLOCKS, 256>>>(x, W, n);
    cudaStreamWaitEvent(0, ev_scan, 0);
    norm_kernel<<<norm_blocks, 256>>>(n);
    cudaStreamWaitEvent(0, ev_fill, 0);
    gather_kernel<<<(n * 32 + 255) / 256, 256>>>(b, out, n);
}

// round 17
// speedup vs baseline: 1.2049x; 1.2049x over previous
#include <cuda_runtime.h>
#include <cuda_bf16.h>
#include <cuda_fp16.h>
#include <cstdint>

// Problem shape (fixed by the dataset): N=100000 nodes, 256 in-feats, 64 out-feats, E=3.2M edges.
#define NMAX   100000
#define EMAX   3200000
#define KIN    256
#define COUT   64
#define NBLK   ((NMAX + 255) / 256)   // 391
#define TM     128
#define TKC    16
#define GEMM_BLOCKS ((NMAX + TM - 1) / TM)   // 782

// Scratch (no cudaMalloc allowed).
__device__ float  g_h[(size_t)NMAX * COUT];  // h = x@W (RAW fp32, kept raw)
__device__ __half g_hh[(size_t)NMAX * COUT]; // h' = h*dinv in fp16 (12.8 MB, L2-resident)
__device__ float  g_dinv[NMAX];              // rsqrt(deg+1)
__device__ int    g_degi[NMAX];              // incoming-edge count (excl. self-loop)
__device__ int    g_off[NMAX];               // CSR offsets (exclusive scan of degi)
__device__ int    g_cur[NMAX];               // fill cursors
__device__ int    g_srcl[EMAX];              // CSR: source node per incoming edge
__device__ unsigned long long g_state[NBLK]; // lookback: (flag<<32)|sum; 1=aggregate,2=prefix
__device__ int    g_tkt;                     // scan ticket
__device__ int    g_idx64;                   // 1 if edge_index is int64, 0 if int32

// ---------------------------------------------------------------------------
// helpers
// ---------------------------------------------------------------------------
__device__ __forceinline__ int load_col(const void* ei, int E, int e) {
    if (g_idx64) return (int)__ldg(&((const long long*)ei)[(size_t)E + e]);
    return __ldg(&((const int*)ei)[(size_t)E + e]);
}
__device__ __forceinline__ int load_row(const void* ei, int e) {
    if (g_idx64) return (int)__ldg(&((const long long*)ei)[e]);
    return __ldg(&((const int*)ei)[e]);
}

__device__ __forceinline__ void split_tf32(float v, float& hi, float& lo) {
    uint32_t u;
    asm("cvt.rna.tf32.f32 %0, %1;" : "=r"(u) : "f"(v));
    hi = __uint_as_float(u);
    float l = v - hi;
    asm("cvt.rna.tf32.f32 %0, %1;" : "=r"(u) : "f"(l));
    lo = __uint_as_float(u);
}

__device__ __forceinline__ void mma_tf32(float* c, const uint32_t* a,
                                         uint32_t b0, uint32_t b1) {
    asm volatile("mma.sync.aligned.m16n8k8.row.col.f32.tf32.tf32.f32 "
                 "{%0,%1,%2,%3}, {%4,%5,%6,%7}, {%8,%9}, {%0,%1,%2,%3};"
                 : "+f"(c[0]), "+f"(c[1]), "+f"(c[2]), "+f"(c[3])
                 : "r"(a[0]), "r"(a[1]), "r"(a[2]), "r"(a[3]),
                   "r"(b0), "r"(b1));
}

// ---------------------------------------------------------------------------
// 1) detect dtype (block 0) + zero degi / scan state (blocks 1..)
// ---------------------------------------------------------------------------
__global__ void detect_zero_kernel(const long long* __restrict__ e64, int n, int nblk) {
    if (blockIdx.x == 0) {
        __shared__ int bad;
        if (threadIdx.x == 0) bad = 0;
        __syncthreads();
        for (int i = threadIdx.x; i < 4096; i += blockDim.x) {
            long long v = e64[i];
            if (v < 0 || v >= (long long)n) atomicOr(&bad, 1);
        }
        __syncthreads();
        if (threadIdx.x == 0) g_idx64 = bad ? 0 : 1;
    } else {
        int i = (blockIdx.x - 1) * 256 + threadIdx.x;
        if (i < n) g_degi[i] = 0;
        if (i < nblk) g_state[i] = 0ULL;
        if (i == 0) g_tkt = 0;
    }
}

// ---------------------------------------------------------------------------
// 2) degi[col[e]] += 1, 4 edges/thread  (fire-and-forget -> REDG)
// ---------------------------------------------------------------------------
__global__ void count_kernel(const void* __restrict__ ei, int E) {
    int e0 = (blockIdx.x * 256 + threadIdx.x) * 4;
#pragma unroll
    for (int k = 0; k < 4; k++) {
        int e = e0 + k;
        if (e < E) atomicAdd(&g_degi[load_col(ei, E, e)], 1);
    }
}

// ---------------------------------------------------------------------------
// 3) gemm: h = x @ W (RAW) via 3xTF32 MMA, 128x64 tile, 8 warps. (pure R8 form)
// ---------------------------------------------------------------------------
__global__ __launch_bounds__(256) void gemm_kernel(const float* __restrict__ x,
                                                   const float* __restrict__ W,
                                                   int n) {
    __shared__ float xs_h[TM][20];    // stride 20: frag reads conflict-free
    __shared__ float xs_l[TM][20];
    __shared__ float ws_h[TKC][72];   // stride 72 (== 8 mod 32): conflict-free
    __shared__ float ws_l[TKC][72];

    const int t    = threadIdx.x;
    const int warp = t >> 5;
    const int lane = t & 31;
    const int lq   = lane >> 2;   // groupID 0..7
    const int kc   = lane & 3;    // threadID_in_group 0..3
    const int wrow = warp * 16;
    const int row0 = blockIdx.x * TM;

    float acc[8][4];
#pragma unroll
    for (int i = 0; i < 8; i++)
#pragma unroll
        for (int j = 0; j < 4; j++) acc[i][j] = 0.0f;

#pragma unroll
    for (int k0 = 0; k0 < KIN; k0 += TKC) {
#pragma unroll
        for (int j = 0; j < 2; j++) {
            int i  = t + j * 256;        // 0..511
            int r  = i >> 2;             // 0..127
            int kq = (i & 3) << 2;       // 0,4,8,12
            int gr = row0 + r;
            float4 v = make_float4(0.f, 0.f, 0.f, 0.f);
            if (gr < n) v = *(const float4*)(x + (size_t)gr * KIN + k0 + kq);
            float4 h4, l4;
            split_tf32(v.x, h4.x, l4.x);
            split_tf32(v.y, h4.y, l4.y);
            split_tf32(v.z, h4.z, l4.z);
            split_tf32(v.w, h4.w, l4.w);
            *(float4*)&xs_h[r][kq] = h4;
            *(float4*)&xs_l[r][kq] = l4;
        }
        {
            int kk = t >> 4;             // 0..15
            int c  = (t & 15) << 2;      // 0..60
            float4 v = *(const float4*)(W + (size_t)(k0 + kk) * COUT + c);
            float4 h4, l4;
            split_tf32(v.x, h4.x, l4.x);
            split_tf32(v.y, h4.y, l4.y);
            split_tf32(v.z, h4.z, l4.z);
            split_tf32(v.w, h4.w, l4.w);
            *(float4*)&ws_h[kk][c] = h4;
            *(float4*)&ws_l[kk][c] = l4;
        }
        __syncthreads();

#pragma unroll
        for (int kk = 0; kk < TKC; kk += 8) {
            uint32_t ah[4], al[4];
            const int rA = wrow + lq;
            ah[0] = __float_as_uint(xs_h[rA][kk + kc]);
            ah[1] = __float_as_uint(xs_h[rA + 8][kk + kc]);
            ah[2] = __float_as_uint(xs_h[rA][kk + kc + 4]);
            ah[3] = __float_as_uint(xs_h[rA + 8][kk + kc + 4]);
            al[0] = __float_as_uint(xs_l[rA][kk + kc]);
            al[1] = __float_as_uint(xs_l[rA + 8][kk + kc]);
            al[2] = __float_as_uint(xs_l[rA][kk + kc + 4]);
            al[3] = __float_as_uint(xs_l[rA + 8][kk + kc + 4]);
#pragma unroll
            for (int nt = 0; nt < 8; nt++) {
                int col = nt * 8 + lq;
                uint32_t bh0 = __float_as_uint(ws_h[kk + kc][col]);
                uint32_t bh1 = __float_as_uint(ws_h[kk + kc + 4][col]);
                uint32_t bl0 = __float_as_uint(ws_l[kk + kc][col]);
                uint32_t bl1 = __float_as_uint(ws_l[kk + kc + 4][col]);
                mma_tf32(acc[nt], ah, bh0, bh1);   // hi*hi
                mma_tf32(acc[nt], al, bh0, bh1);   // lo*hi
                mma_tf32(acc[nt], ah, bl0, bl1);   // hi*lo
            }
        }
        __syncthreads();
    }

    // epilogue: store RAW h (fp16 h' produced by norm kernel)
    const int gr0 = row0 + wrow + lq;
    const int gr1 = gr0 + 8;
#pragma unroll
    for (int nt = 0; nt < 8; nt++) {
        int col = nt * 8 + kc * 2;
        if (gr0 < n) *(float2*)(g_h + (size_t)gr0 * COUT + col) = make_float2(acc[nt][0], acc[nt][1]);
        if (gr1 < n) *(float2*)(g_h + (size_t)gr1 * COUT + col) = make_float2(acc[nt][2], acc[nt][3]);
    }
}

// ---------------------------------------------------------------------------
// 4) single-pass exclusive scan (decoupled lookback, ticket-ordered blocks)
//    emits g_off, g_cur, g_dinv.
// ---------------------------------------------------------------------------
__global__ __launch_bounds__(256) void scan_kernel(int n) {
    __shared__ int sbid;
    __shared__ int wsum[8];
    __shared__ int sbase;
    if (threadIdx.x == 0) sbid = atomicAdd(&g_tkt, 1);
    __syncthreads();
    const int bid = sbid;
    const int i = bid * 256 + threadIdx.x;
    const int lane = threadIdx.x & 31, wid = threadIdx.x >> 5;

    int v = (i < n) ? g_degi[i] : 0;
    int p = v;
#pragma unroll
    for (int o = 1; o < 32; o <<= 1) {
        int t = __shfl_up_sync(0xffffffffu, p, o);
        if (lane >= o) p += t;
    }
    if (lane == 31) wsum[wid] = p;
    __syncthreads();
    if (wid == 0) {
        int s = (lane < 8) ? wsum[lane] : 0;
#pragma unroll
        for (int o = 1; o < 8; o <<= 1) {
            int t = __shfl_up_sync(0xffffffffu, s, o);
            if (lane >= o) s += t;
        }
        if (lane < 8) wsum[lane] = s;   // inclusive warp sums
    }
    __syncthreads();
    const int base  = wid ? wsum[wid - 1] : 0;
    const int total = wsum[7];          // block sum

    if (threadIdx.x == 0) {
        if (bid == 0) {
            atomicExch(&g_state[0], (2ULL << 32) | (unsigned)total);
            sbase = 0;
        } else {
            atomicExch(&g_state[bid], (1ULL << 32) | (unsigned)total);
            int run = 0;
            for (int j = bid - 1;; j--) {
                unsigned long long s;
                do { s = *(volatile unsigned long long*)&g_state[j]; } while ((s >> 32) == 0);
                run += (int)(unsigned)s;
                if ((s >> 32) == 2ULL) break;
            }
            atomicExch(&g_state[bid], (2ULL << 32) | (unsigned)(run + total));
            sbase = run;
        }
    }
    __syncthreads();
    if (i < n) {
        int o = sbase + base + p - v;   // exclusive prefix
        g_off[i]  = o;
        g_cur[i]  = o;
        g_dinv[i] = rsqrtf((float)v + 1.0f);
    }
}

// ---------------------------------------------------------------------------
// 5) norm: g_hh = (fp16)(g_h * dinv[node]).  One float4 (4 cols) per thread,
//    writes 4 halves (8B). g_h stays RAW fp32 (used for the self-loop term).
// ---------------------------------------------------------------------------
__global__ void norm_kernel(int n) {
    int idx = blockIdx.x * 256 + threadIdx.x;        // over N*16 float4s
    if (idx < n * (COUT / 4)) {
        int node = idx >> 4;
        float d = g_dinv[node];
        float4 v = *(const float4*)(g_h + (size_t)idx * 4);
        __half2 h0 = __floats2half2_rn(v.x * d, v.y * d);
        __half2 h1 = __floats2half2_rn(v.z * d, v.w * d);
        *(__half2*)(g_hh + (size_t)idx * 4)     = h0;
        *(__half2*)(g_hh + (size_t)idx * 4 + 2) = h1;
    }
}

// ---------------------------------------------------------------------------
// 6) fill CSR: g_srcl[cur[col]++] = row, 4 edges/thread  (R14 exact)
// ---------------------------------------------------------------------------
__global__ void fill_kernel(const void* __restrict__ ei, int E) {
    int e0 = (blockIdx.x * 256 + threadIdx.x) * 4;
#pragma unroll
    for (int k = 0; k < 4; k++) {
        int e = e0 + k;
        if (e < E) {
            int r = load_row(ei, e);
            int c = load_col(ei, E, e);
            int pos = atomicAdd(&g_cur[c], 1);
            g_srcl[pos] = r;
        }
    }
}

// ---------------------------------------------------------------------------
// 7) gather + finalize: one warp per node, __half2 lanes, 4-way unroll
//    (R14 load pattern; 4B loads instead of 8B -> half the L2 traffic).
//    Accumulation in fp32; self-loop term from RAW fp32 g_h.
//    out[i] = (sum_s h'[s] + h[i]*dinv[i]) * dinv[i] + b
// ---------------------------------------------------------------------------
__global__ __launch_bounds__(256) void gather_kernel(const float* __restrict__ b,
                                                     float* __restrict__ out, int n) {
    int warp = (blockIdx.x * 256 + threadIdx.x) >> 5;
    int lane = threadIdx.x & 31;
    if (warp >= n) return;

    const int beg = g_off[warp];
    const int d   = g_degi[warp];

    float2 a0 = make_float2(0.f, 0.f);
    float2 a1 = make_float2(0.f, 0.f);
    float2 a2 = make_float2(0.f, 0.f);
    float2 a3 = make_float2(0.f, 0.f);

    for (int j0 = 0; j0 < d; j0 += 32) {
        int m  = min(32, d - j0);
        int sl = (lane < m) ? g_srcl[beg + j0 + lane] : 0;
        int j  = 0;
        for (; j + 3 < m; j += 4) {
            int s0 = __shfl_sync(0xffffffffu, sl, j);
            int s1 = __shfl_sync(0xffffffffu, sl, j + 1);
            int s2 = __shfl_sync(0xffffffffu, sl, j + 2);
            int s3 = __shfl_sync(0xffffffffu, sl, j + 3);
            __half2 h0 = *(const __half2*)(g_hh + (size_t)s0 * COUT + lane * 2);
            __half2 h1 = *(const __half2*)(g_hh + (size_t)s1 * COUT + lane * 2);
            __half2 h2 = *(const __half2*)(g_hh + (size_t)s2 * COUT + lane * 2);
            __half2 h3 = *(const __half2*)(g_hh + (size_t)s3 * COUT + lane * 2);
            float2 v0 = __half22float2(h0);
            float2 v1 = __half22float2(h1);
            float2 v2 = __half22float2(h2);
            float2 v3 = __half22float2(h3);
            a0.x += v0.x; a0.y += v0.y;
            a1.x += v1.x; a1.y += v1.y;
            a2.x += v2.x; a2.y += v2.y;
            a3.x += v3.x; a3.y += v3.y;
        }
        for (; j < m; j++) {
            int s0 = __shfl_sync(0xffffffffu, sl, j);
            __half2 h0 = *(const __half2*)(g_hh + (size_t)s0 * COUT + lane * 2);
            float2 v0 = __half22float2(h0);
            a0.x += v0.x; a0.y += v0.y;
        }
    }

    // self-loop in full fp32 precision from RAW h
    float2 hs = *(const float2*)(g_h + (size_t)warp * COUT + lane * 2);
    float dinv = g_dinv[warp];
    float2 bb = *(const float2*)(b + lane * 2);
    float2 o;
    o.x = (a0.x + a1.x + a2.x + a3.x + hs.x * dinv) * dinv + bb.x;
    o.y = (a0.y + a1.y + a2.y + a3.y + hs.y * dinv) * dinv + bb.y;
    *(float2*)(out + (size_t)warp * COUT + lane * 2) = o;
}

// ---------------------------------------------------------------------------
// Launch: fork-join two streams inside graph capture. (R14 topology)
//   origin (legacy) stream: gemm ............ wait(scan) norm  wait(fill) gather
//   side stream sB:         detect count scan [ev_scan]  fill  [ev_fill]
// ---------------------------------------------------------------------------
extern "C" void kernel_launch(void* const* d_in, const int* in_sizes, int n_in,
                              void* d_out, int out_size) {
    const float* x  = (const float*)d_in[0];
    const void*  ei = d_in[1];                 // int64 or int32, detected on device
    const float* W  = (const float*)d_in[2];
    const float* b  = (const float*)d_in[3];
    float* out = (float*)d_out;

    const int n = in_sizes[0] / KIN;           // 100000
    const int E = in_sizes[1] / 2;             // 3200000
    const int nblk = (n + 255) / 256;          // 391
    const int edge_blocks = (E + 1023) / 1024; // 4 edges/thread
    const int norm_blocks = (n * (COUT / 4) + 255) / 256;

    // One-time resource creation (host-side only; no device memory).
    static cudaStream_t sB = nullptr;
    static cudaEvent_t ev_start = nullptr, ev_scan = nullptr, ev_fill = nullptr;
    if (sB == nullptr) {
        cudaStreamCreateWithFlags(&sB, cudaStreamNonBlocking);
        cudaEventCreateWithFlags(&ev_start, cudaEventDisableTiming);
        cudaEventCreateWithFlags(&ev_scan,  cudaEventDisableTiming);
        cudaEventCreateWithFlags(&ev_fill,  cudaEventDisableTiming);
    }

    // Fork side stream from origin.
    cudaEventRecord(ev_start, 0);
    cudaStreamWaitEvent(sB, ev_start, 0);

    // Side chain: detect -> count -> scan -> fill
    detect_zero_kernel<<<nblk + 1, 256, 0, sB>>>((const long long*)ei, n, nblk);
    count_kernel<<<edge_blocks, 256, 0, sB>>>(ei, E);
    scan_kernel<<<nblk, 256, 0, sB>>>(n);
    cudaEventRecord(ev_scan, sB);
    fill_kernel<<<edge_blocks, 256, 0, sB>>>(ei, E);
    cudaEventRecord(ev_fill, sB);

    // Origin chain: gemm (overlaps side chain) -> norm -> gather
    gemm_kernel<<<GEMM_BLOCKS, 256>>>(x, W, n);
    cudaStreamWaitEvent(0, ev_scan, 0);
    norm_kernel<<<norm_blocks, 256>>>(n);
    cudaStreamWaitEvent(0, ev_fill, 0);
    gather_kernel<<<(n * 32 + 255) / 256, 256>>>(b, out, n);
}